// round 2
// baseline (speedup 1.0000x reference)
#include <cuda_runtime.h>
#include <stdint.h>

#define BDIM    256      // batch rows
#define SDIM    2048     // sequence positions
#define VDIM    128000   // vocab
#define THREADS 512
#define PER     (SDIM / THREADS)   // 4 positions per thread
#define HSIZE   4096               // smem hash slots (load factor 0.5)
#define NWARPS  (THREADS / 32)

__device__ __forceinline__ float block_reduce_max(float v, float* red) {
    __syncthreads();  // protect red[] reuse across calls
    #pragma unroll
    for (int o = 16; o; o >>= 1)
        v = fmaxf(v, __shfl_xor_sync(0xffffffffu, v, o));
    int w = threadIdx.x >> 5, l = threadIdx.x & 31;
    if (l == 0) red[w] = v;
    __syncthreads();
    if (w == 0) {
        v = (l < NWARPS) ? red[l] : -1e30f;
        #pragma unroll
        for (int o = 16; o; o >>= 1)
            v = fmaxf(v, __shfl_xor_sync(0xffffffffu, v, o));
        if (l == 0) red[0] = v;
    }
    __syncthreads();
    return red[0];
}

__device__ __forceinline__ float block_reduce_sum(float v, float* red) {
    __syncthreads();
    #pragma unroll
    for (int o = 16; o; o >>= 1)
        v += __shfl_xor_sync(0xffffffffu, v, o);
    int w = threadIdx.x >> 5, l = threadIdx.x & 31;
    if (l == 0) red[w] = v;
    __syncthreads();
    if (w == 0) {
        v = (l < NWARPS) ? red[l] : 0.0f;
        #pragma unroll
        for (int o = 16; o; o >>= 1)
            v += __shfl_xor_sync(0xffffffffu, v, o);
        if (l == 0) red[0] = v;
    }
    __syncthreads();
    return red[0];
}

__global__ __launch_bounds__(THREADS, 2)
void ohwa_kernel(const float* __restrict__ w_es,
                 const int* __restrict__ x32,   // raw int32 view of x buffer
                 float* __restrict__ out,
                 long long out_elems) {
    const int b = blockIdx.x;
    const int t = threadIdx.x;

    // --- dtype sniff: int64 little-endian high words are 0 for v < 2^31 ---
    // Four odd-index words all zero => int64 buffer. False-positive prob ~0.
    const bool is64 = (x32[1] | x32[3] | x32[5] | x32[7]) == 0;
    const int stride = is64 ? 2 : 1;
    const int* __restrict__ xrow = x32 + (size_t)b * SDIM * stride;

    float* __restrict__ w_a  = out + (size_t)b * VDIM;
    const float* __restrict__ wrow = w_es + (size_t)b * SDIM;

    __shared__ int   h_key[HSIZE];
    __shared__ int   h_pos[HSIZE];
    __shared__ float red[NWARPS];

    // --- zero this row's vocab slice (dominant HBM cost), vectorized ---
    float4 z4 = make_float4(0.f, 0.f, 0.f, 0.f);
    float4* wa4 = reinterpret_cast<float4*>(w_a);
    #pragma unroll 4
    for (int i = t; i < VDIM / 4; i += THREADS)
        wa4[i] = z4;

    // --- init hash ---
    for (int i = t; i < HSIZE; i += THREADS) {
        h_key[i] = -1;
        h_pos[i] = -1;
    }
    // (block_reduce_* below begins with __syncthreads(), covering zero+init)

    // --- load scores + indices ---
    float e[PER];
    int   vv[PER];
    float m = -1e30f;
    #pragma unroll
    for (int j = 0; j < PER; j++) {
        int i = t + j * THREADS;
        e[j]  = wrow[i];
        vv[j] = xrow[i * stride];          // low word (little-endian) either way
        m = fmaxf(m, e[j]);
    }

    // --- softmax ---
    m = block_reduce_max(m, red);
    float s = 0.0f;
    #pragma unroll
    for (int j = 0; j < PER; j++) {
        e[j] = __expf(e[j] - m);
        s += e[j];
    }
    s = block_reduce_sum(s, red);
    float inv = __frcp_rn(s);

    // --- write weights region (guarded by actual out size) ---
    long long wbase = (long long)BDIM * VDIM + (long long)b * SDIM;
    #pragma unroll
    for (int j = 0; j < PER; j++) {
        e[j] *= inv;                       // e[j] is now the weight
        long long o = wbase + t + j * THREADS;
        if (o < out_elems) out[o] = e[j];
    }

    // --- duplicate resolution: last position wins (matches in-order scatter) ---
    int slot[PER];
    #pragma unroll
    for (int j = 0; j < PER; j++) {
        int v = vv[j];
        int i = t + j * THREADS;
        if ((unsigned)v >= VDIM) { slot[j] = -1; continue; }
        unsigned sl = ((unsigned)v * 2654435761u) & (HSIZE - 1);
        while (true) {
            int k = h_key[sl];
            if (k == v) break;
            if (k == -1) {
                int old = atomicCAS(&h_key[sl], -1, v);
                if (old == -1 || old == v) break;
            }
            sl = (sl + 1) & (HSIZE - 1);
        }
        slot[j] = (int)sl;
        atomicMax(&h_pos[sl], i);
    }
    __syncthreads();

    // --- scatter winners ---
    #pragma unroll
    for (int j = 0; j < PER; j++) {
        int i = t + j * THREADS;
        if (slot[j] >= 0 && h_pos[slot[j]] == i)
            w_a[vv[j]] = e[j];
    }
}

extern "C" void kernel_launch(void* const* d_in, const int* in_sizes, int n_in,
                              void* d_out, int out_size) {
    const float* w_es = (const float*)d_in[0];
    const int*   x32  = (const int*)d_in[1];
    float*       out  = (float*)d_out;
    (void)in_sizes; (void)n_in;
    ohwa_kernel<<<BDIM, THREADS>>>(w_es, x32, out, (long long)out_size);
}